// round 14
// baseline (speedup 1.0000x reference)
#include <cuda_runtime.h>
#include <math.h>

#define NN 1024
#define DD 64
#define DPP 32
#define NB_TILE 136
#define NB_TAIL 128

// ---------------- scratch (device globals) ---------------------------------
__device__ float    g_dH[NN * NN];        // 4 MB pairwise H distances (mirrored)
__device__ float    g_dP[NN * NN];        // 4 MB pairwise P distances (mirrored)
__device__ unsigned g_mask [NN * 32];     // row-major top-K bitset (fully overwritten)
__device__ unsigned g_maskT[NN * 32];     // transposed bitset (atomicOr; zeroed in k_main)
__device__ float    g_x[NN * DD];         // XX @ weight
__device__ float    g_y[NN * DD];         // x @ psi_w^T
__device__ float    g_bmxH[NB_TILE];      // per-H-block max
__device__ float    g_bmxP[NB_TILE];      // per-P-block max
__device__ float    g_bnp[NB_TAIL][2][DD];   // per-block BN partials (s1, s2)
__device__ unsigned g_arr1, g_arr2;       // tail handshake counters (zeroed in k_main)

// ---------------- 1. merged: H-dist | P-dist | xy+init (336 blocks) --------
__global__ __launch_bounds__(256)
void k_main(const float* __restrict__ XH, const float* __restrict__ XP,
            const float* __restrict__ XX, const float* __restrict__ W,
            const float* __restrict__ PW) {
    __shared__ float pool[10304];         // 41.2 KB, phase-aliased
    __shared__ float sNA[64], sNB[64];
    __shared__ unsigned smx[8];
    int t = threadIdx.x;
    int bid = blockIdx.x;

    if (bid >= 2 * NB_TILE) {
        // ---------------- xy body + init ----------------
        int xb = bid - 2 * NB_TILE;       // 0..63
        int gt = xb * 256 + t;            // 16384 threads
        g_maskT[gt * 2]     = 0u;
        g_maskT[gt * 2 + 1] = 0u;
        if (gt == 0) { g_arr1 = 0u; g_arr2 = 0u; }

        float* sW  = pool;                // [k*64+d], 4096
        float* sPW = pool + 4096;         // [d*65+k], 4160 (padded)
        float* sXX = pool + 8256;         // 1024
        float* sx  = pool + 9280;         // 1024
        int row0 = xb * 16;

        for (int idx = t; idx < 4096; idx += 256) sW[idx] = W[idx];
        for (int idx = t; idx < 4096; idx += 256) {
            int d = idx >> 6, k = idx & 63;
            sPW[d * 65 + k] = PW[idx];
        }
        for (int idx = t; idx < 1024; idx += 256) sXX[idx] = XX[row0 * 64 + idx];
        __syncthreads();

        int d = t & 63, rg = t >> 6;
        float acc[4] = {0.f, 0.f, 0.f, 0.f};
        #pragma unroll
        for (int k = 0; k < 64; ++k) {
            float wv = sW[k * 64 + d];
            #pragma unroll
            for (int rr = 0; rr < 4; ++rr) acc[rr] += sXX[(rg * 4 + rr) * 64 + k] * wv;
        }
        #pragma unroll
        for (int rr = 0; rr < 4; ++rr) {
            sx[(rg * 4 + rr) * 64 + d] = acc[rr];
            g_x[(row0 + rg * 4 + rr) * 64 + d] = acc[rr];
        }
        __syncthreads();

        float a2[4] = {0.f, 0.f, 0.f, 0.f};
        #pragma unroll
        for (int k = 0; k < 64; ++k) {
            float pw = sPW[d * 65 + k];
            #pragma unroll
            for (int rr = 0; rr < 4; ++rr) a2[rr] += sx[(rg * 4 + rr) * 64 + k] * pw;
        }
        #pragma unroll
        for (int rr = 0; rr < 4; ++rr) g_y[(row0 + rg * 4 + rr) * 64 + d] = a2[rr];
        return;
    }

    // ---------------- dist body: one feature family per block --------------
    int isH = (bid < NB_TILE);
    int tid = isH ? bid : bid - NB_TILE;
    int by = 0, rem = tid;
    while (rem >= 16 - by) { rem -= 16 - by; ++by; }
    int bx = by + rem;
    int i0 = by * 64, j0 = bx * 64;
    int tx = t & 15, ty = t >> 4;

    float acc[4][4];
    #pragma unroll
    for (int a = 0; a < 4; ++a)
        #pragma unroll
        for (int b = 0; b < 4; ++b) acc[a][b] = 0.f;

    if (isH) {
        const float sig = (float)(0.1 + 2.220446049250313e-16);  // sigma + f64 eps
        float (*sA)[66] = (float(*)[66])pool;              // even stride: float2 ok
        float (*sB)[66] = (float(*)[66])(pool + 64 * 66);
        for (int idx = t; idx < 4096; idx += 256) {
            int r = idx >> 6, d = idx & 63;
            sA[r][d] = XH[(i0 + r) * 64 + d] / sig;
            sB[r][d] = XH[(j0 + r) * 64 + d] / sig;
        }
        __syncthreads();

        // row norms (threads 0..127, 4 partial chains)
        if (t < 128) {
            const float* rp = (t < 64) ? &sA[t][0] : &sB[t - 64][0];
            float n0 = 0.f, n1 = 0.f, n2 = 0.f, n3 = 0.f;
            #pragma unroll
            for (int d = 0; d < 64; d += 4) {
                n0 += rp[d] * rp[d];
                n1 += rp[d + 1] * rp[d + 1];
                n2 += rp[d + 2] * rp[d + 2];
                n3 += rp[d + 3] * rp[d + 3];
            }
            float nv = (n0 + n1) + (n2 + n3);
            if (t < 64) sNA[t] = nv; else sNB[t - 64] = nv;
        }

        #pragma unroll 4
        for (int d = 0; d < 64; d += 2) {
            float2 rI[4], rJ[4];
            #pragma unroll
            for (int a = 0; a < 4; ++a) rI[a] = *(const float2*)&sA[ty + 16 * a][d];
            #pragma unroll
            for (int b = 0; b < 4; ++b) rJ[b] = *(const float2*)&sB[tx + 16 * b][d];
            #pragma unroll
            for (int a = 0; a < 4; ++a)
                #pragma unroll
                for (int b = 0; b < 4; ++b) {
                    acc[a][b] += rI[a].x * rJ[b].x;   // dim d
                    acc[a][b] += rI[a].y * rJ[b].y;   // dim d+1 (ascending order kept)
                }
        }
    } else {
        float (*pA)[34] = (float(*)[34])pool;              // even stride
        float (*pB)[34] = (float(*)[34])(pool + 64 * 34);
        for (int idx = t; idx < 2048; idx += 256) {
            int r = idx >> 5, p = idx & 31;
            pA[r][p] = XP[(i0 + r) * 32 + p];
            pB[r][p] = XP[(j0 + r) * 32 + p];
        }
        __syncthreads();

        if (t < 128) {
            const float* rp = (t < 64) ? &pA[t][0] : &pB[t - 64][0];
            float n0 = 0.f, n1 = 0.f, n2 = 0.f, n3 = 0.f;
            #pragma unroll
            for (int p = 0; p < 32; p += 4) {
                n0 += rp[p] * rp[p];
                n1 += rp[p + 1] * rp[p + 1];
                n2 += rp[p + 2] * rp[p + 2];
                n3 += rp[p + 3] * rp[p + 3];
            }
            float nv = (n0 + n1) + (n2 + n3);
            if (t < 64) sNA[t] = nv; else sNB[t - 64] = nv;
        }

        #pragma unroll 4
        for (int p = 0; p < 32; p += 2) {
            float2 rI[4], rJ[4];
            #pragma unroll
            for (int a = 0; a < 4; ++a) rI[a] = *(const float2*)&pA[ty + 16 * a][p];
            #pragma unroll
            for (int b = 0; b < 4; ++b) rJ[b] = *(const float2*)&pB[tx + 16 * b][p];
            #pragma unroll
            for (int a = 0; a < 4; ++a)
                #pragma unroll
                for (int b = 0; b < 4; ++b) {
                    acc[a][b] += rI[a].x * rJ[b].x;
                    acc[a][b] += rI[a].y * rJ[b].y;
                }
        }
    }
    __syncthreads();                      // norms visible

    float* dst = isH ? g_dH : g_dP;

    // d = sqrt(max(nI + nJ - 2*dot, 0)), write, per-block max
    float nA[4], nB[4];
    #pragma unroll
    for (int a = 0; a < 4; ++a) nA[a] = sNA[ty + 16 * a];
    #pragma unroll
    for (int b = 0; b < 4; ++b) nB[b] = sNB[tx + 16 * b];

    float res[4][4];
    unsigned lmx = 0u;
    #pragma unroll
    for (int a = 0; a < 4; ++a)
        #pragma unroll
        for (int b = 0; b < 4; ++b) {
            float dv = sqrtf(fmaxf(nA[a] + nB[b] - 2.f * acc[a][b], 0.f));
            res[a][b] = dv;
            lmx = max(lmx, __float_as_uint(dv));
            dst[(i0 + ty + 16 * a) * NN + (j0 + tx + 16 * b)] = dv;
        }
    lmx = __reduce_max_sync(0xffffffffu, lmx);
    if ((t & 31) == 0) smx[t >> 5] = lmx;
    __syncthreads();
    if (t == 0) {
        unsigned h = 0u;
        #pragma unroll
        for (int wv = 0; wv < 8; ++wv) h = max(h, smx[wv]);
        if (isH) g_bmxH[tid] = __uint_as_float(h);
        else     g_bmxP[tid] = __uint_as_float(h);
    }

    // mirror tile via shared transpose (coalesced both ways)
    if (bx != by) {
        __syncthreads();
        float (*st)[65] = (float(*)[65])pool;
        #pragma unroll
        for (int a = 0; a < 4; ++a)
            #pragma unroll
            for (int b = 0; b < 4; ++b)
                st[tx + 16 * b][ty + 16 * a] = res[a][b];
        __syncthreads();
        for (int idx = t; idx < 4096; idx += 256) {
            int r = idx >> 6, c = idx & 63;
            dst[(j0 + r) * NN + (i0 + c)] = st[r][c];
        }
    }
}

// ---------------- 2. merged topk + deg + BN + output (128 blocks) ----------
__global__ __launch_bounds__(256)
void k_tail(const int* __restrict__ Kp,
            const float* __restrict__ psi_b, const float* __restrict__ gamma,
            const float* __restrict__ beta, const float* __restrict__ bias,
            const float* __restrict__ XP, float* __restrict__ out) {
    __shared__ unsigned sredH[8], sredP[8];
    __shared__ int   sc[8], sdg[8];
    __shared__ float sp1[8][64], sp2[8][64];
    __shared__ float ss1[4][64], ss2[4][64];
    __shared__ float smu[64], sistd[64], sg[64], sb[64], sbi[64], spb[64];
    int t = threadIdx.x, lane = t & 31, w = t >> 5;
    int i = blockIdx.x * 8 + w;

    // ---- max prologue ----
    {
        unsigned h = 0u, p = 0u;
        if (t < NB_TILE) {
            h = __float_as_uint(g_bmxH[t]);
            p = __float_as_uint(g_bmxP[t]);
        }
        h = __reduce_max_sync(0xffffffffu, h);
        p = __reduce_max_sync(0xffffffffu, p);
        if (lane == 0) { sredH[w] = h; sredP[w] = p; }
    }
    __syncthreads();
    unsigned hh = 0u, pp = 0u;
    #pragma unroll
    for (int s = 0; s < 8; ++s) { hh = max(hh, sredH[s]); pp = max(pp, sredP[s]); }
    float invH = 0.5f / __uint_as_float(hh);   // min is exactly 0 (diagonal)
    float invP = 1.0f / __uint_as_float(pp);

    // ---- topk: one warp per row ----
    unsigned key[32];
    #pragma unroll
    for (int s = 0; s < 32; ++s) {
        float dh = g_dH[i * NN + s * 32 + lane];
        float dp = g_dP[i * NN + s * 32 + lane];
        float ww = expf(-dh * invH) + 0.2f * expf(-dp * invP);
        key[s] = __float_as_uint(ww);
    }

    int K = Kp ? Kp[0] : 16;
    if (K < 1) K = 1; if (K > NN) K = NN;

    unsigned mrow = 0u;                   // lane L accumulates mask word L
    for (int it = 0; it < K; ++it) {
        unsigned lm = 0u;
        #pragma unroll
        for (int s = 0; s < 32; ++s) lm = max(lm, key[s]);
        unsigned wm = __reduce_max_sync(0xffffffffu, lm);
        int jc = 0x7fffffff;
        #pragma unroll
        for (int s = 0; s < 32; ++s)
            if (key[s] == wm && s * 32 + lane < jc) jc = s * 32 + lane;
        int jmin = __reduce_min_sync(0xffffffffu, (unsigned)jc);
        int ssel = jmin >> 5;
        if (lane == (jmin & 31)) {
            #pragma unroll
            for (int s = 0; s < 32; ++s)
                if (s == ssel) key[s] = 0u;
        }
        if (lane == ssel) mrow |= 1u << (jmin & 31);
        if (lane == 0)
            atomicOr(&g_maskT[jmin * 32 + (i >> 5)], 1u << (i & 31));
    }
    g_mask[i * 32 + lane] = mrow;

    // ---- handshake 1: all masks complete ----
    __syncthreads();
    if (t == 0) {
        __threadfence();
        atomicAdd(&g_arr1, 1u);
        while (*(volatile unsigned*)&g_arr1 < NB_TAIL) { }
        __threadfence();
    }
    __syncthreads();

    // ---- degrees + diag for own 8 rows (warp w: row j0+w) ----
    int j0 = blockIdx.x * 8;
    {
        int j = j0 + w;
        unsigned m = g_mask[j * 32 + lane] | g_maskT[j * 32 + lane];
        int c = __reduce_add_sync(0xffffffffu, __popc(m));
        int db = __shfl_sync(0xffffffffu, (int)((m >> (j & 31)) & 1u), j >> 5);
        if (lane == 0) { sc[w] = c; sdg[w] = db; }
    }
    __syncthreads();

    // ---- BN partials over own 8 rows (float2 per thread) ----
    {
        float2 y2 = ((const float2*)g_y)[blockIdx.x * 256 + t];
        int jl = t >> 5, d0 = (t & 31) * 2;
        float c = (float)sc[jl];
        float yv[2] = {y2.x, y2.y};
        #pragma unroll
        for (int u = 0; u < 2; ++u) {
            float bb = psi_b[d0 + u];
            sp1[jl][d0 + u] = yv[u] * ((float)NN + c);
            float h1 = yv[u] + bb, h2 = 2.f * yv[u] + bb;
            sp2[jl][d0 + u] = ((float)NN - c) * h1 * h1 + c * h2 * h2;
        }
    }
    __syncthreads();
    if (t < 64) {
        float a1 = ((sp1[0][t] + sp1[1][t]) + (sp1[2][t] + sp1[3][t]))
                 + ((sp1[4][t] + sp1[5][t]) + (sp1[6][t] + sp1[7][t]));
        float a2 = ((sp2[0][t] + sp2[1][t]) + (sp2[2][t] + sp2[3][t]))
                 + ((sp2[4][t] + sp2[5][t]) + (sp2[6][t] + sp2[7][t]));
        g_bnp[blockIdx.x][0][t] = a1;
        g_bnp[blockIdx.x][1][t] = a2;
    }
    __syncthreads();

    // ---- handshake 2: all partials published ----
    if (t == 0) {
        __threadfence();
        atomicAdd(&g_arr2, 1u);
        while (*(volatile unsigned*)&g_arr2 < NB_TAIL) { }
        __threadfence();
    }
    __syncthreads();

    // ---- redundant parallel finalize (all 256 threads; 4 stripes of 32) ---
    {
        int d = t & 63, stripe = t >> 6;
        float s1 = 0.f, s2 = 0.f;
        #pragma unroll 4
        for (int bl = stripe * 32; bl < stripe * 32 + 32; ++bl) {
            s1 += g_bnp[bl][0][d];
            s2 += g_bnp[bl][1][d];
        }
        ss1[stripe][d] = s1; ss2[stripe][d] = s2;
    }
    __syncthreads();
    if (t < 64) {
        float s1 = ss1[0][t] + ss1[1][t] + ss1[2][t] + ss1[3][t];
        float s2 = ss2[0][t] + ss2[1][t] + ss2[2][t] + ss2[3][t];
        const float invN2 = 1.0f / ((float)NN * (float)NN);
        float mu  = psi_b[t] + s1 * invN2;
        float var = s2 * invN2 - mu * mu;
        smu[t]   = mu;
        sistd[t] = rsqrtf(var + 1e-5f);
        sg[t] = gamma[t]; sb[t] = beta[t]; sbi[t] = bias[t]; spb[t] = psi_b[t];
    }
    __syncthreads();

    // ---- output own 8 rows (threads 0..127, one float4 each) ----
    if (t < 128) {
        int q = blockIdx.x * 128 + t;     // global float4 slot
        int jl = t >> 4, d0 = (t & 15) * 4;
        float4 y4 = ((const float4*)g_y)[q];
        float4 x4 = ((const float4*)g_x)[q];
        float dg = (float)sdg[jl], c = (float)sc[jl];
        float yv[4] = {y4.x, y4.y, y4.z, y4.w};
        float xv[4] = {x4.x, x4.y, x4.z, x4.w};
        float4 o4;
        float* ov = (float*)&o4;
        #pragma unroll
        for (int u = 0; u < 4; ++u) {
            int d = d0 + u;
            float z = (2.f * yv[u] + spb[d] - smu[d]) * sistd[d] * sg[d] + sb[d];
            float s = 1.0f / (1.0f + expf(-z));
            ov[u] = xv[u] * (dg + (c - dg) * s) + sbi[d];
        }
        ((float4*)out)[q] = o4;                               // out[:, :DH] segment
        ((float4*)(out + NN * DD + NN * DPP))[q] = o4;        // full out segment
        if (q < NN * DPP / 4)
            ((float4*)(out + NN * DD))[q] = ((const float4*)XP)[q];  // XP passthrough
    }
}

// ---------------- launch ----------------------------------------------------
extern "C" void kernel_launch(void* const* d_in, const int* in_sizes, int n_in,
                              void* d_out, int out_size) {
    // expected order: XH, XP, XX, K, weight, bias, psi_w, psi_b, gamma, beta
    int iXH = 0, iXP = 1, iXX = 2, iK = 3, iW = 4, iB = 5, iPW = 6, iPB = 7, iG = 8, iBe = 9;
    if (n_in == 9) {  // K dropped as a scalar
        iK = -1; iW = 3; iB = 4; iPW = 5; iPB = 6; iG = 7; iBe = 8;
    }
    const float* XH  = (const float*)d_in[iXH];
    const float* XP  = (const float*)d_in[iXP];
    const float* XX  = (const float*)d_in[iXX];
    const int*   Kp  = (iK >= 0) ? (const int*)d_in[iK] : nullptr;
    const float* W   = (const float*)d_in[iW];
    const float* B   = (const float*)d_in[iB];
    const float* PW  = (const float*)d_in[iPW];
    const float* PB  = (const float*)d_in[iPB];
    const float* G   = (const float*)d_in[iG];
    const float* Be  = (const float*)d_in[iBe];
    float* out = (float*)d_out;

    k_main<<<2 * NB_TILE + 64, 256>>>(XH, XP, XX, W, PW);
    k_tail<<<NB_TAIL, 256>>>(Kp, PB, G, Be, B, XP, out);
    (void)in_sizes; (void)out_size;
}